// round 5
// baseline (speedup 1.0000x reference)
#include <cuda_runtime.h>
#include <math.h>

// ---------------- problem constants ----------------
constexpr int NN   = 20000;
constexpr int EE   = 320000;
constexpr int NT   = 200000;
constexpr int IND  = 512;   // INPUT_DIM
constexpr int HID  = 128;
constexpr int DC   = 256;
constexpr int HEADS = 8;
constexpr int DK   = 16;

// ---------------- scratch (static device globals; no runtime alloc) --------
__device__ float g_W12[512 * 512];
__device__ float g_b12[512];
__device__ float g_Wtftg[256 * 256];
__device__ float g_btftg[256];
__device__ float g_Wab[128 * 128];
__device__ float g_bab[128];

__device__ float g_h[(size_t)NN * 512];    // [h_gcn1 | h_gcn2]
__device__ float g_agg[(size_t)NN * 512];  // segment sums
__device__ float g_dinv[NN];

__device__ float g_g1[(size_t)NN * 256];   // sigmoid(gcn1)
__device__ float g_xa[(size_t)NN * 256];   // gcn2 raw
__device__ float g_xg[(size_t)NN * 128];
__device__ float g_tftg[(size_t)NN * 256]; // [tf | tg]

__device__ float g_qin[(size_t)NN * 128];
__device__ float g_kin[(size_t)NN * 128];
__device__ float g_vin[(size_t)NN * 128];
__device__ float g_q[(size_t)NN * 128];
__device__ float g_k[(size_t)NN * 128];
__device__ float g_v[(size_t)NN * 128];

__device__ float g_kc[DC * 128];
__device__ float g_vc[DC * 128];

__device__ float g_att[(size_t)NN * 128];
__device__ float g_xf[(size_t)NN * 128];
__device__ float g_ab[(size_t)NN * 128];   // [tfa | tga], leaky applied
__device__ float g_na[NN];
__device__ float g_nb[NN];

// ---------------- small helpers ----------------
__global__ void zero_kernel(float* __restrict__ p, int n) {
    int i = blockIdx.x * blockDim.x + threadIdx.x;
    if (i < n) p[i] = 0.0f;
}

// pack W = [W1 | W2] (rows x 2*hc), b = [b1 | b2]
__global__ void pack2(float* __restrict__ W, const float* __restrict__ W1,
                      const float* __restrict__ W2, float* __restrict__ b,
                      const float* __restrict__ b1, const float* __restrict__ b2,
                      int rows, int hc) {
    int idx = blockIdx.x * blockDim.x + threadIdx.x;
    int tot = rows * 2 * hc;
    if (idx < tot) {
        int r = idx / (2 * hc);
        int c = idx - r * 2 * hc;
        W[idx] = (c < hc) ? W1[r * hc + c] : W2[r * hc + (c - hc)];
    }
    if (idx < 2 * hc) b[idx] = (idx < hc) ? b1[idx] : b2[idx - hc];
}

// ---------------- degree ----------------
__global__ void deg_init() {
    int i = blockIdx.x * blockDim.x + threadIdx.x;
    if (i < NN) g_dinv[i] = 1.0f;
}
__global__ void deg_count(const int* __restrict__ adj) {
    int e = blockIdx.x * blockDim.x + threadIdx.x;
    if (e < EE) atomicAdd(&g_dinv[adj[EE + e]], 1.0f);
}
__global__ void deg_finish() {
    int i = blockIdx.x * blockDim.x + threadIdx.x;
    if (i < NN) g_dinv[i] = rsqrtf(g_dinv[i]);
}

// ---------------- edge scatter: agg[dst] += h[src] * dinv[src]*dinv[dst] ----
// 128 threads per edge (512 floats = 128 float4)
__global__ void edge_scatter(const int* __restrict__ adj) {
    long long gid = (long long)blockIdx.x * blockDim.x + threadIdx.x;
    int e = (int)(gid >> 7);
    int lane = (int)(gid & 127);
    if (e >= EE) return;
    int s = adj[e];
    int d = adj[EE + e];
    float coef = g_dinv[s] * g_dinv[d];
    const float4 hv = *(const float4*)(g_h + (size_t)s * 512 + lane * 4);
    float* dst = g_agg + (size_t)d * 512 + lane * 4;
    atomicAdd(dst + 0, hv.x * coef);
    atomicAdd(dst + 1, hv.y * coef);
    atomicAdd(dst + 2, hv.z * coef);
    atomicAdd(dst + 3, hv.w * coef);
}

// ---------------- gcn finalize: agg + h*dinv^2 + b; sigmoid split ----------
__global__ void finalize_gcn() {
    int idx = blockIdx.x * blockDim.x + threadIdx.x;
    if (idx >= NN * 512) return;
    int n = idx >> 9;
    int j = idx & 511;
    float di = g_dinv[n];
    float v = g_agg[idx] + g_h[idx] * di * di + g_b12[j];
    if (j < 256) g_g1[(size_t)n * 256 + j] = 1.0f / (1.0f + __expf(-v));
    else         g_xa[(size_t)n * 256 + (j - 256)] = v;
}

// ---------------- qkv inputs ----------------
__global__ void build_qkv(const int* __restrict__ positions,
                          const float* __restrict__ pos_emb) {
    int idx = blockIdx.x * blockDim.x + threadIdx.x;
    if (idx >= NN * 128) return;
    int n = idx >> 7;
    int j = idx & 127;
    float pe = pos_emb[positions[n] * 128 + j];
    g_qin[idx] = g_xg[idx] + pe;
    g_kin[idx] = g_tftg[(size_t)n * 256 + j] + pe;
    g_vin[idx] = g_tftg[(size_t)n * 256 + 128 + j];
}

// ---------------- generic fp32 SGEMM: C = act(A@B + bias) ------------------
// BM=BN=128, BK=8, 256 threads, 8x8 per thread. N % 128 == 0, K % 8 == 0.
template <int ACT>
__global__ void __launch_bounds__(256)
sgemm(const float* __restrict__ A, const float* __restrict__ B,
      const float* __restrict__ bias, float* __restrict__ C,
      int M, int N, int K) {
    __shared__ float As[8][128];
    __shared__ float Bs[8][128];
    const int tid = threadIdx.x;
    const int rowBase = blockIdx.y * 128;
    const int colBase = blockIdx.x * 128;

    const int lr = tid >> 1;           // 0..127 (A row within tile)
    const int lq = (tid & 1) * 4;      // 0 or 4 (k offset)
    const int br = tid >> 5;           // 0..7   (B k-row)
    const int bc = (tid & 31) * 4;     // 0..124 (B col)
    const int rm = tid >> 4;           // 0..15
    const int rn = tid & 15;           // 0..15

    const int arow = rowBase + lr;
    const bool aval = arow < M;
    const float* Aptr = A + (size_t)arow * K + lq;

    float acc[8][8];
#pragma unroll
    for (int i = 0; i < 8; i++)
#pragma unroll
        for (int j = 0; j < 8; j++) acc[i][j] = 0.0f;

    for (int k0 = 0; k0 < K; k0 += 8) {
        float4 a4 = aval ? *(const float4*)(Aptr + k0) : make_float4(0, 0, 0, 0);
        float4 b4 = *(const float4*)(B + (size_t)(k0 + br) * N + colBase + bc);
        __syncthreads();
        As[lq + 0][lr] = a4.x;
        As[lq + 1][lr] = a4.y;
        As[lq + 2][lr] = a4.z;
        As[lq + 3][lr] = a4.w;
        *(float4*)&Bs[br][bc] = b4;
        __syncthreads();
#pragma unroll
        for (int k = 0; k < 8; k++) {
            float4 a0 = *(float4*)&As[k][rm * 8];
            float4 a1 = *(float4*)&As[k][rm * 8 + 4];
            float4 b0 = *(float4*)&Bs[k][rn * 8];
            float4 b1 = *(float4*)&Bs[k][rn * 8 + 4];
            float av[8] = {a0.x, a0.y, a0.z, a0.w, a1.x, a1.y, a1.z, a1.w};
            float bv[8] = {b0.x, b0.y, b0.z, b0.w, b1.x, b1.y, b1.z, b1.w};
#pragma unroll
            for (int i = 0; i < 8; i++)
#pragma unroll
                for (int j = 0; j < 8; j++) acc[i][j] += av[i] * bv[j];
        }
    }

#pragma unroll
    for (int i = 0; i < 8; i++) {
        int row = rowBase + rm * 8 + i;
        if (row >= M) continue;
#pragma unroll
        for (int j4 = 0; j4 < 2; j4++) {
            int col = colBase + rn * 8 + j4 * 4;
            float4 o;
            float* op = &o.x;
#pragma unroll
            for (int j = 0; j < 4; j++) {
                float v = acc[i][j4 * 4 + j] + (bias ? bias[col + j] : 0.0f);
                if (ACT == 1) v = (v >= 0.0f) ? v : 0.01f * v;
                op[j] = v;
            }
            *(float4*)&C[(size_t)row * N + col] = o;
        }
    }
}

// ---------------- split-K GEMM for kc = Ek@k, vc = Ev@v --------------------
// M=256(DC), N=128, K=20000. BM=BN=64, BK=32, 25 k-iters per split, 25 splits.
__global__ void __launch_bounds__(256)
splitk_ckv(const float* __restrict__ Ekm, const float* __restrict__ Evm) {
    const int mat = blockIdx.z & 1;
    const int split = blockIdx.z >> 1;
    const float* Am = mat ? Evm : Ekm;
    const float* Xm = mat ? g_v : g_k;
    float* Cm = mat ? g_vc : g_kc;

    const int rowBase = blockIdx.y * 64;   // 4 tiles
    const int colBase = blockIdx.x * 64;   // 2 tiles
    const int tid = threadIdx.x;
    const int rm = tid >> 4, rn = tid & 15;

    __shared__ float As[32][64];
    __shared__ float Bs[32][64];

    float acc[4][4];
#pragma unroll
    for (int i = 0; i < 4; i++)
#pragma unroll
        for (int j = 0; j < 4; j++) acc[i][j] = 0.0f;

    const int kstart = split * 25 * 32;
    for (int it = 0; it < 25; it++) {
        int kbase = kstart + it * 32;
        __syncthreads();
#pragma unroll
        for (int pp = 0; pp < 2; pp++) {
            int p = tid + pp * 256;
            int row = p >> 3;
            int kq = (p & 7) * 4;
            float4 a4 = *(const float4*)(Am + (size_t)(rowBase + row) * NN + kbase + kq);
            As[kq + 0][row] = a4.x;
            As[kq + 1][row] = a4.y;
            As[kq + 2][row] = a4.z;
            As[kq + 3][row] = a4.w;
            int krow = p >> 4;
            int cq = (p & 15) * 4;
            float4 b4 = *(const float4*)(Xm + (size_t)(kbase + krow) * 128 + colBase + cq);
            *(float4*)&Bs[krow][cq] = b4;
        }
        __syncthreads();
#pragma unroll
        for (int k = 0; k < 32; k++) {
            float4 a4 = *(float4*)&As[k][rm * 4];
            float4 b4 = *(float4*)&Bs[k][rn * 4];
            float av[4] = {a4.x, a4.y, a4.z, a4.w};
            float bv[4] = {b4.x, b4.y, b4.z, b4.w};
#pragma unroll
            for (int i = 0; i < 4; i++)
#pragma unroll
                for (int j = 0; j < 4; j++) acc[i][j] += av[i] * bv[j];
        }
    }
#pragma unroll
    for (int i = 0; i < 4; i++)
#pragma unroll
        for (int j = 0; j < 4; j++)
            atomicAdd(&Cm[(size_t)(rowBase + rm * 4 + i) * 128 + colBase + rn * 4 + j],
                      acc[i][j]);
}

// ---------------- fused attention (online softmax) -------------------------
// block: 128 nodes x 1 head. kc/vc head slices staged in SMEM.
__global__ void __launch_bounds__(128)
attn_kernel() {
    __shared__ float4 kcs[DC][4];
    __shared__ float4 vcs[DC][4];
    const int h = blockIdx.y;
    const int tid = threadIdx.x;
    for (int p = tid; p < DC * 4; p += 128) {
        int c = p >> 2, d = p & 3;
        kcs[c][d] = *(const float4*)(g_kc + c * 128 + h * 16 + d * 4);
        vcs[c][d] = *(const float4*)(g_vc + c * 128 + h * 16 + d * 4);
    }
    __syncthreads();
    int n = blockIdx.x * 128 + tid;
    if (n >= NN) return;

    const float* qp = g_q + (size_t)n * 128 + h * 16;
    float4 q0 = *(const float4*)(qp + 0);
    float4 q1 = *(const float4*)(qp + 4);
    float4 q2 = *(const float4*)(qp + 8);
    float4 q3 = *(const float4*)(qp + 12);

    float m = -1e30f, s = 0.0f;
    float4 o0 = {0, 0, 0, 0}, o1 = {0, 0, 0, 0}, o2 = {0, 0, 0, 0}, o3 = {0, 0, 0, 0};

    for (int c = 0; c < DC; c++) {
        float4 k0 = kcs[c][0], k1 = kcs[c][1], k2 = kcs[c][2], k3 = kcs[c][3];
        float dot = q0.x * k0.x + q0.y * k0.y + q0.z * k0.z + q0.w * k0.w
                  + q1.x * k1.x + q1.y * k1.y + q1.z * k1.z + q1.w * k1.w
                  + q2.x * k2.x + q2.y * k2.y + q2.z * k2.z + q2.w * k2.w
                  + q3.x * k3.x + q3.y * k3.y + q3.z * k3.z + q3.w * k3.w;
        float sc = dot * 0.25f;
        float mn = fmaxf(m, sc);
        float al = __expf(m - mn);
        float p = __expf(sc - mn);
        s = s * al + p;
        float4 v0 = vcs[c][0], v1 = vcs[c][1], v2 = vcs[c][2], v3 = vcs[c][3];
        o0.x = o0.x * al + p * v0.x; o0.y = o0.y * al + p * v0.y;
        o0.z = o0.z * al + p * v0.z; o0.w = o0.w * al + p * v0.w;
        o1.x = o1.x * al + p * v1.x; o1.y = o1.y * al + p * v1.y;
        o1.z = o1.z * al + p * v1.z; o1.w = o1.w * al + p * v1.w;
        o2.x = o2.x * al + p * v2.x; o2.y = o2.y * al + p * v2.y;
        o2.z = o2.z * al + p * v2.z; o2.w = o2.w * al + p * v2.w;
        o3.x = o3.x * al + p * v3.x; o3.y = o3.y * al + p * v3.y;
        o3.z = o3.z * al + p * v3.z; o3.w = o3.w * al + p * v3.w;
        m = mn;
    }
    float inv = 1.0f / s;
    float* op = g_att + (size_t)n * 128 + h * 16;
    o0.x *= inv; o0.y *= inv; o0.z *= inv; o0.w *= inv;
    o1.x *= inv; o1.y *= inv; o1.z *= inv; o1.w *= inv;
    o2.x *= inv; o2.y *= inv; o2.z *= inv; o2.w *= inv;
    o3.x *= inv; o3.y *= inv; o3.z *= inv; o3.w *= inv;
    *(float4*)(op + 0) = o0;
    *(float4*)(op + 4) = o1;
    *(float4*)(op + 8) = o2;
    *(float4*)(op + 12) = o3;
}

// ---------------- row norms of tfa / tga ----------------
__global__ void norms_kernel() {
    int n = blockIdx.x * blockDim.x + threadIdx.x;
    if (n >= NN) return;
    const float4* a = (const float4*)(g_ab + (size_t)n * 128);
    float sa = 0.0f, sb = 0.0f;
#pragma unroll
    for (int i = 0; i < 16; i++) {
        float4 v = a[i];
        sa += v.x * v.x + v.y * v.y + v.z * v.z + v.w * v.w;
    }
#pragma unroll
    for (int i = 16; i < 32; i++) {
        float4 v = a[i];
        sb += v.x * v.x + v.y * v.y + v.z * v.z + v.w * v.w;
    }
    g_na[n] = sqrtf(sa);
    g_nb[n] = sqrtf(sb);
}

// ---------------- final cosine for 200K pairs ----------------
__global__ void final_pairs(const int* __restrict__ ts, float* __restrict__ out) {
    int t = blockIdx.x * blockDim.x + threadIdx.x;
    if (t >= NT) return;
    int i = ts[2 * t];
    int j = ts[2 * t + 1];
    const float4* a = (const float4*)(g_ab + (size_t)i * 128);
    const float4* b = (const float4*)(g_ab + (size_t)j * 128 + 64);
    float dot = 0.0f;
#pragma unroll
    for (int p = 0; p < 16; p++) {
        float4 av = a[p];
        float4 bv = b[p];
        dot += av.x * bv.x + av.y * bv.y + av.z * bv.z + av.w * bv.w;
    }
    out[t] = dot / fmaxf(g_na[i] * g_nb[j], 1e-8f);
}

// ---------------- host launcher ----------------
static float* symaddr(const void* sym) {
    void* p = nullptr;
    cudaGetSymbolAddress(&p, sym);
    return (float*)p;
}

extern "C" void kernel_launch(void* const* d_in, const int* in_sizes, int n_in,
                              void* d_out, int out_size) {
    const int*   train_sample = (const int*)d_in[1];
    const float* data_feature = (const float*)d_in[2];
    const int*   adj          = (const int*)d_in[3];
    const int*   positions    = (const int*)d_in[4];
    const float* gcn_W   = (const float*)d_in[5];
    const float* gcn_b   = (const float*)d_in[6];
    const float* gcnA2_W = (const float*)d_in[7];
    const float* gcnA2_b = (const float*)d_in[8];
    const float* lin_W   = (const float*)d_in[9];
    const float* lin_b   = (const float*)d_in[10];
    const float* tf_W    = (const float*)d_in[11];
    const float* tf_b    = (const float*)d_in[12];
    const float* tg_W    = (const float*)d_in[13];
    const float* tg_b    = (const float*)d_in[14];
    const float* Wq = (const float*)d_in[15];
    const float* bq = (const float*)d_in[16];
    const float* Wk = (const float*)d_in[17];
    const float* bk = (const float*)d_in[18];
    const float* Wv = (const float*)d_in[19];
    const float* bv = (const float*)d_in[20];
    const float* Wo = (const float*)d_in[21];
    const float* bo = (const float*)d_in[22];
    const float* Ek = (const float*)d_in[23];
    const float* Ev = (const float*)d_in[24];
    const float* pos_emb = (const float*)d_in[25];
    const float* tfa_W = (const float*)d_in[26];
    const float* tfa_b = (const float*)d_in[27];
    const float* tga_W = (const float*)d_in[28];
    const float* tga_b = (const float*)d_in[29];

    float* d_W12   = symaddr(g_W12);
    float* d_b12   = symaddr(g_b12);
    float* d_Wtftg = symaddr(g_Wtftg);
    float* d_btftg = symaddr(g_btftg);
    float* d_Wab   = symaddr(g_Wab);
    float* d_bab   = symaddr(g_bab);
    float* d_h    = symaddr(g_h);
    float* d_agg  = symaddr(g_agg);
    float* d_g1   = symaddr(g_g1);
    float* d_xa   = symaddr(g_xa);
    float* d_xg   = symaddr(g_xg);
    float* d_tftg = symaddr(g_tftg);
    float* d_qin  = symaddr(g_qin);
    float* d_kin  = symaddr(g_kin);
    float* d_vin  = symaddr(g_vin);
    float* d_q    = symaddr(g_q);
    float* d_k    = symaddr(g_k);
    float* d_v    = symaddr(g_v);
    float* d_kc   = symaddr(g_kc);
    float* d_vc   = symaddr(g_vc);
    float* d_att  = symaddr(g_att);
    float* d_xf   = symaddr(g_xf);
    float* d_ab   = symaddr(g_ab);

    // 1. pack fused weight blocks
    pack2<<<(512 * 512 + 255) / 256, 256>>>(d_W12, gcn_W, gcnA2_W, d_b12, gcn_b, gcnA2_b, 512, 256);
    pack2<<<(256 * 256 + 255) / 256, 256>>>(d_Wtftg, tf_W, tg_W, d_btftg, tf_b, tg_b, 256, 128);
    pack2<<<(128 * 128 + 255) / 256, 256>>>(d_Wab, tfa_W, tga_W, d_bab, tfa_b, tga_b, 128, 64);

    // 2. h = data_feature @ [gcn_W | gcnA2_W]  (20000 x 512 x 512)
    sgemm<0><<<dim3(4, 157), 256>>>(data_feature, d_W12, nullptr, d_h, NN, 512, IND);

    // 3. degrees
    deg_init<<<(NN + 255) / 256, 256>>>();
    deg_count<<<(EE + 255) / 256, 256>>>(adj);
    deg_finish<<<(NN + 255) / 256, 256>>>();

    // 4. segment sum
    zero_kernel<<<(NN * 512 + 255) / 256, 256>>>(d_agg, NN * 512);
    edge_scatter<<<(EE * 128 + 255) / 256, 256>>>(adj);

    // 5. gcn finalize -> g1 (sigmoid), xa
    finalize_gcn<<<(NN * 512 + 255) / 256, 256>>>();

    // 6. x_g = leaky(g1 @ lin_W + lin_b); [tf|tg] = leaky(xa @ [tf_W|tg_W] + b)
    sgemm<1><<<dim3(1, 157), 256>>>(d_g1, lin_W, lin_b, d_xg, NN, 128, 256);
    sgemm<1><<<dim3(2, 157), 256>>>(d_xa, d_Wtftg, d_btftg, d_tftg, NN, 256, 256);

    // 7. q/k/v inputs (+pos emb) and projections
    build_qkv<<<(NN * 128 + 255) / 256, 256>>>(positions, pos_emb);
    sgemm<0><<<dim3(1, 157), 256>>>(d_qin, Wq, bq, d_q, NN, 128, 128);
    sgemm<0><<<dim3(1, 157), 256>>>(d_kin, Wk, bk, d_k, NN, 128, 128);
    sgemm<0><<<dim3(1, 157), 256>>>(d_vin, Wv, bv, d_v, NN, 128, 128);

    // 8. kc = Ek@k, vc = Ev@v  (split-K, atomic accumulate)
    zero_kernel<<<(DC * 128 * 2 + 255) / 256, 256>>>(d_kc, DC * 128);
    zero_kernel<<<(DC * 128 + 255) / 256, 256>>>(d_vc, DC * 128);
    splitk_ckv<<<dim3(2, 4, 50), 256>>>(Ek, Ev);

    // 9. fused attention
    attn_kernel<<<dim3(157, HEADS), 128>>>();

    // 10. x_f = att @ Wo + bo; [tfa|tga] = leaky(x_f @ [tfa_W|tga_W] + b)
    sgemm<0><<<dim3(1, 157), 256>>>(d_att, Wo, bo, d_xf, NN, 128, 128);
    sgemm<1><<<dim3(1, 157), 256>>>(d_xf, d_Wab, d_bab, d_ab, NN, 128, 128);

    // 11. norms + final cosine pairs
    norms_kernel<<<(NN + 255) / 256, 256>>>();
    final_pairs<<<(NT + 255) / 256, 256>>>(train_sample, (float*)d_out);
}

// round 6
// speedup vs baseline: 1.0032x; 1.0032x over previous
#include <cuda_runtime.h>
#include <math.h>

// ---------------- problem constants ----------------
constexpr int NN   = 20000;
constexpr int EE   = 320000;
constexpr int NT   = 200000;
constexpr int IND  = 512;   // INPUT_DIM
constexpr int HID  = 128;
constexpr int DC   = 256;
constexpr int HEADS = 8;
constexpr int DK   = 16;

// ---------------- scratch (static device globals; no runtime alloc) --------
__device__ float g_W12[512 * 512];
__device__ float g_b12[512];
__device__ float g_Wtftg[256 * 256];
__device__ float g_btftg[256];
__device__ float g_Wab[128 * 128];
__device__ float g_bab[128];

__device__ float g_h[(size_t)NN * 512];    // [h_gcn1 | h_gcn2]
__device__ float g_agg[(size_t)NN * 512];  // segment sums
__device__ float g_dinv[NN];

__device__ float g_g1[(size_t)NN * 256];   // sigmoid(gcn1)
__device__ float g_xa[(size_t)NN * 256];   // gcn2 raw
__device__ float g_xg[(size_t)NN * 128];
__device__ float g_tftg[(size_t)NN * 256]; // [tf | tg]

__device__ float g_qin[(size_t)NN * 128];
__device__ float g_kin[(size_t)NN * 128];
__device__ float g_vin[(size_t)NN * 128];
__device__ float g_q[(size_t)NN * 128];
__device__ float g_k[(size_t)NN * 128];
__device__ float g_v[(size_t)NN * 128];

__device__ float g_kc[DC * 128];
__device__ float g_vc[DC * 128];

__device__ float g_att[(size_t)NN * 128];
__device__ float g_xf[(size_t)NN * 128];
__device__ float g_ab[(size_t)NN * 128];   // [tfa | tga], leaky applied
__device__ float g_na[NN];
__device__ float g_nb[NN];

// ---------------- small helpers ----------------
__global__ void zero_kernel(float* __restrict__ p, int n) {
    int i = blockIdx.x * blockDim.x + threadIdx.x;
    if (i < n) p[i] = 0.0f;
}

// pack W = [W1 | W2] (rows x 2*hc), b = [b1 | b2]
__global__ void pack2(float* __restrict__ W, const float* __restrict__ W1,
                      const float* __restrict__ W2, float* __restrict__ b,
                      const float* __restrict__ b1, const float* __restrict__ b2,
                      int rows, int hc) {
    int idx = blockIdx.x * blockDim.x + threadIdx.x;
    int tot = rows * 2 * hc;
    if (idx < tot) {
        int r = idx / (2 * hc);
        int c = idx - r * 2 * hc;
        W[idx] = (c < hc) ? W1[r * hc + c] : W2[r * hc + (c - hc)];
    }
    if (idx < 2 * hc) b[idx] = (idx < hc) ? b1[idx] : b2[idx - hc];
}

// ---------------- degree ----------------
__global__ void deg_init() {
    int i = blockIdx.x * blockDim.x + threadIdx.x;
    if (i < NN) g_dinv[i] = 1.0f;
}
__global__ void deg_count(const int* __restrict__ adj) {
    int e = blockIdx.x * blockDim.x + threadIdx.x;
    if (e < EE) atomicAdd(&g_dinv[adj[EE + e]], 1.0f);
}
__global__ void deg_finish() {
    int i = blockIdx.x * blockDim.x + threadIdx.x;
    if (i < NN) g_dinv[i] = rsqrtf(g_dinv[i]);
}

// ---------------- edge scatter: agg[dst] += h[src] * dinv[src]*dinv[dst] ----
// 128 threads per edge (512 floats = 128 float4)
__global__ void edge_scatter(const int* __restrict__ adj) {
    long long gid = (long long)blockIdx.x * blockDim.x + threadIdx.x;
    int e = (int)(gid >> 7);
    int lane = (int)(gid & 127);
    if (e >= EE) return;
    int s = adj[e];
    int d = adj[EE + e];
    float coef = g_dinv[s] * g_dinv[d];
    const float4 hv = *(const float4*)(g_h + (size_t)s * 512 + lane * 4);
    float* dst = g_agg + (size_t)d * 512 + lane * 4;
    atomicAdd(dst + 0, hv.x * coef);
    atomicAdd(dst + 1, hv.y * coef);
    atomicAdd(dst + 2, hv.z * coef);
    atomicAdd(dst + 3, hv.w * coef);
}

// ---------------- gcn finalize: agg + h*dinv^2 + b; sigmoid split ----------
__global__ void finalize_gcn() {
    int idx = blockIdx.x * blockDim.x + threadIdx.x;
    if (idx >= NN * 512) return;
    int n = idx >> 9;
    int j = idx & 511;
    float di = g_dinv[n];
    float v = g_agg[idx] + g_h[idx] * di * di + g_b12[j];
    if (j < 256) g_g1[(size_t)n * 256 + j] = 1.0f / (1.0f + __expf(-v));
    else         g_xa[(size_t)n * 256 + (j - 256)] = v;
}

// ---------------- qkv inputs ----------------
__global__ void build_qkv(const int* __restrict__ positions,
                          const float* __restrict__ pos_emb) {
    int idx = blockIdx.x * blockDim.x + threadIdx.x;
    if (idx >= NN * 128) return;
    int n = idx >> 7;
    int j = idx & 127;
    float pe = pos_emb[positions[n] * 128 + j];
    g_qin[idx] = g_xg[idx] + pe;
    g_kin[idx] = g_tftg[(size_t)n * 256 + j] + pe;
    g_vin[idx] = g_tftg[(size_t)n * 256 + 128 + j];
}

// ---------------- generic fp32 SGEMM: C = act(A@B + bias) ------------------
// BM=BN=128, BK=8, 256 threads, 8x8 per thread. N % 128 == 0, K % 8 == 0.
template <int ACT>
__global__ void __launch_bounds__(256)
sgemm(const float* __restrict__ A, const float* __restrict__ B,
      const float* __restrict__ bias, float* __restrict__ C,
      int M, int N, int K) {
    __shared__ float As[8][128];
    __shared__ float Bs[8][128];
    const int tid = threadIdx.x;
    const int rowBase = blockIdx.y * 128;
    const int colBase = blockIdx.x * 128;

    const int lr = tid >> 1;           // 0..127 (A row within tile)
    const int lq = (tid & 1) * 4;      // 0 or 4 (k offset)
    const int br = tid >> 5;           // 0..7   (B k-row)
    const int bc = (tid & 31) * 4;     // 0..124 (B col)
    const int rm = tid >> 4;           // 0..15
    const int rn = tid & 15;           // 0..15

    const int arow = rowBase + lr;
    const bool aval = arow < M;
    const float* Aptr = A + (size_t)arow * K + lq;

    float acc[8][8];
#pragma unroll
    for (int i = 0; i < 8; i++)
#pragma unroll
        for (int j = 0; j < 8; j++) acc[i][j] = 0.0f;

    for (int k0 = 0; k0 < K; k0 += 8) {
        float4 a4 = aval ? *(const float4*)(Aptr + k0) : make_float4(0, 0, 0, 0);
        float4 b4 = *(const float4*)(B + (size_t)(k0 + br) * N + colBase + bc);
        __syncthreads();
        As[lq + 0][lr] = a4.x;
        As[lq + 1][lr] = a4.y;
        As[lq + 2][lr] = a4.z;
        As[lq + 3][lr] = a4.w;
        *(float4*)&Bs[br][bc] = b4;
        __syncthreads();
#pragma unroll
        for (int k = 0; k < 8; k++) {
            float4 a0 = *(float4*)&As[k][rm * 8];
            float4 a1 = *(float4*)&As[k][rm * 8 + 4];
            float4 b0 = *(float4*)&Bs[k][rn * 8];
            float4 b1 = *(float4*)&Bs[k][rn * 8 + 4];
            float av[8] = {a0.x, a0.y, a0.z, a0.w, a1.x, a1.y, a1.z, a1.w};
            float bv[8] = {b0.x, b0.y, b0.z, b0.w, b1.x, b1.y, b1.z, b1.w};
#pragma unroll
            for (int i = 0; i < 8; i++)
#pragma unroll
                for (int j = 0; j < 8; j++) acc[i][j] += av[i] * bv[j];
        }
    }

#pragma unroll
    for (int i = 0; i < 8; i++) {
        int row = rowBase + rm * 8 + i;
        if (row >= M) continue;
#pragma unroll
        for (int j4 = 0; j4 < 2; j4++) {
            int col = colBase + rn * 8 + j4 * 4;
            float4 o;
            float* op = &o.x;
#pragma unroll
            for (int j = 0; j < 4; j++) {
                float v = acc[i][j4 * 4 + j] + (bias ? bias[col + j] : 0.0f);
                if (ACT == 1) v = (v >= 0.0f) ? v : 0.01f * v;
                op[j] = v;
            }
            *(float4*)&C[(size_t)row * N + col] = o;
        }
    }
}

// ---------------- split-K GEMM for kc = Ek@k, vc = Ev@v --------------------
// M=256(DC), N=128, K=20000. BM=BN=64, BK=32, 25 k-iters per split, 25 splits.
__global__ void __launch_bounds__(256)
splitk_ckv(const float* __restrict__ Ekm, const float* __restrict__ Evm) {
    const int mat = blockIdx.z & 1;
    const int split = blockIdx.z >> 1;
    const float* Am = mat ? Evm : Ekm;
    const float* Xm = mat ? g_v : g_k;
    float* Cm = mat ? g_vc : g_kc;

    const int rowBase = blockIdx.y * 64;   // 4 tiles
    const int colBase = blockIdx.x * 64;   // 2 tiles
    const int tid = threadIdx.x;
    const int rm = tid >> 4, rn = tid & 15;

    __shared__ float As[32][64];
    __shared__ float Bs[32][64];

    float acc[4][4];
#pragma unroll
    for (int i = 0; i < 4; i++)
#pragma unroll
        for (int j = 0; j < 4; j++) acc[i][j] = 0.0f;

    const int kstart = split * 25 * 32;
    for (int it = 0; it < 25; it++) {
        int kbase = kstart + it * 32;
        __syncthreads();
#pragma unroll
        for (int pp = 0; pp < 2; pp++) {
            int p = tid + pp * 256;
            int row = p >> 3;
            int kq = (p & 7) * 4;
            float4 a4 = *(const float4*)(Am + (size_t)(rowBase + row) * NN + kbase + kq);
            As[kq + 0][row] = a4.x;
            As[kq + 1][row] = a4.y;
            As[kq + 2][row] = a4.z;
            As[kq + 3][row] = a4.w;
            int krow = p >> 4;
            int cq = (p & 15) * 4;
            float4 b4 = *(const float4*)(Xm + (size_t)(kbase + krow) * 128 + colBase + cq);
            *(float4*)&Bs[krow][cq] = b4;
        }
        __syncthreads();
#pragma unroll
        for (int k = 0; k < 32; k++) {
            float4 a4 = *(float4*)&As[k][rm * 4];
            float4 b4 = *(float4*)&Bs[k][rn * 4];
            float av[4] = {a4.x, a4.y, a4.z, a4.w};
            float bv[4] = {b4.x, b4.y, b4.z, b4.w};
#pragma unroll
            for (int i = 0; i < 4; i++)
#pragma unroll
                for (int j = 0; j < 4; j++) acc[i][j] += av[i] * bv[j];
        }
    }
#pragma unroll
    for (int i = 0; i < 4; i++)
#pragma unroll
        for (int j = 0; j < 4; j++)
            atomicAdd(&Cm[(size_t)(rowBase + rm * 4 + i) * 128 + colBase + rn * 4 + j],
                      acc[i][j]);
}

// ---------------- fused attention (online softmax) -------------------------
// block: 128 nodes x 1 head. kc/vc head slices staged in SMEM.
__global__ void __launch_bounds__(128)
attn_kernel() {
    __shared__ float4 kcs[DC][4];
    __shared__ float4 vcs[DC][4];
    const int h = blockIdx.y;
    const int tid = threadIdx.x;
    for (int p = tid; p < DC * 4; p += 128) {
        int c = p >> 2, d = p & 3;
        kcs[c][d] = *(const float4*)(g_kc + c * 128 + h * 16 + d * 4);
        vcs[c][d] = *(const float4*)(g_vc + c * 128 + h * 16 + d * 4);
    }
    __syncthreads();
    int n = blockIdx.x * 128 + tid;
    if (n >= NN) return;

    const float* qp = g_q + (size_t)n * 128 + h * 16;
    float4 q0 = *(const float4*)(qp + 0);
    float4 q1 = *(const float4*)(qp + 4);
    float4 q2 = *(const float4*)(qp + 8);
    float4 q3 = *(const float4*)(qp + 12);

    float m = -1e30f, s = 0.0f;
    float4 o0 = {0, 0, 0, 0}, o1 = {0, 0, 0, 0}, o2 = {0, 0, 0, 0}, o3 = {0, 0, 0, 0};

    for (int c = 0; c < DC; c++) {
        float4 k0 = kcs[c][0], k1 = kcs[c][1], k2 = kcs[c][2], k3 = kcs[c][3];
        float dot = q0.x * k0.x + q0.y * k0.y + q0.z * k0.z + q0.w * k0.w
                  + q1.x * k1.x + q1.y * k1.y + q1.z * k1.z + q1.w * k1.w
                  + q2.x * k2.x + q2.y * k2.y + q2.z * k2.z + q2.w * k2.w
                  + q3.x * k3.x + q3.y * k3.y + q3.z * k3.z + q3.w * k3.w;
        float sc = dot * 0.25f;
        float mn = fmaxf(m, sc);
        float al = __expf(m - mn);
        float p = __expf(sc - mn);
        s = s * al + p;
        float4 v0 = vcs[c][0], v1 = vcs[c][1], v2 = vcs[c][2], v3 = vcs[c][3];
        o0.x = o0.x * al + p * v0.x; o0.y = o0.y * al + p * v0.y;
        o0.z = o0.z * al + p * v0.z; o0.w = o0.w * al + p * v0.w;
        o1.x = o1.x * al + p * v1.x; o1.y = o1.y * al + p * v1.y;
        o1.z = o1.z * al + p * v1.z; o1.w = o1.w * al + p * v1.w;
        o2.x = o2.x * al + p * v2.x; o2.y = o2.y * al + p * v2.y;
        o2.z = o2.z * al + p * v2.z; o2.w = o2.w * al + p * v2.w;
        o3.x = o3.x * al + p * v3.x; o3.y = o3.y * al + p * v3.y;
        o3.z = o3.z * al + p * v3.z; o3.w = o3.w * al + p * v3.w;
        m = mn;
    }
    float inv = 1.0f / s;
    float* op = g_att + (size_t)n * 128 + h * 16;
    o0.x *= inv; o0.y *= inv; o0.z *= inv; o0.w *= inv;
    o1.x *= inv; o1.y *= inv; o1.z *= inv; o1.w *= inv;
    o2.x *= inv; o2.y *= inv; o2.z *= inv; o2.w *= inv;
    o3.x *= inv; o3.y *= inv; o3.z *= inv; o3.w *= inv;
    *(float4*)(op + 0) = o0;
    *(float4*)(op + 4) = o1;
    *(float4*)(op + 8) = o2;
    *(float4*)(op + 12) = o3;
}

// ---------------- row norms of tfa / tga ----------------
__global__ void norms_kernel() {
    int n = blockIdx.x * blockDim.x + threadIdx.x;
    if (n >= NN) return;
    const float4* a = (const float4*)(g_ab + (size_t)n * 128);
    float sa = 0.0f, sb = 0.0f;
#pragma unroll
    for (int i = 0; i < 16; i++) {
        float4 v = a[i];
        sa += v.x * v.x + v.y * v.y + v.z * v.z + v.w * v.w;
    }
#pragma unroll
    for (int i = 16; i < 32; i++) {
        float4 v = a[i];
        sb += v.x * v.x + v.y * v.y + v.z * v.z + v.w * v.w;
    }
    g_na[n] = sqrtf(sa);
    g_nb[n] = sqrtf(sb);
}

// ---------------- final cosine for 200K pairs ----------------
__global__ void final_pairs(const int* __restrict__ ts, float* __restrict__ out) {
    int t = blockIdx.x * blockDim.x + threadIdx.x;
    if (t >= NT) return;
    int i = ts[2 * t];
    int j = ts[2 * t + 1];
    const float4* a = (const float4*)(g_ab + (size_t)i * 128);
    const float4* b = (const float4*)(g_ab + (size_t)j * 128 + 64);
    float dot = 0.0f;
#pragma unroll
    for (int p = 0; p < 16; p++) {
        float4 av = a[p];
        float4 bv = b[p];
        dot += av.x * bv.x + av.y * bv.y + av.z * bv.z + av.w * bv.w;
    }
    out[t] = dot / fmaxf(g_na[i] * g_nb[j], 1e-8f);
}

// ---------------- host launcher ----------------
static float* symaddr(const void* sym) {
    void* p = nullptr;
    cudaGetSymbolAddress(&p, sym);
    return (float*)p;
}

extern "C" void kernel_launch(void* const* d_in, const int* in_sizes, int n_in,
                              void* d_out, int out_size) {
    const int*   train_sample = (const int*)d_in[1];
    const float* data_feature = (const float*)d_in[2];
    const int*   adj          = (const int*)d_in[3];
    const int*   positions    = (const int*)d_in[4];
    const float* gcn_W   = (const float*)d_in[5];
    const float* gcn_b   = (const float*)d_in[6];
    const float* gcnA2_W = (const float*)d_in[7];
    const float* gcnA2_b = (const float*)d_in[8];
    const float* lin_W   = (const float*)d_in[9];
    const float* lin_b   = (const float*)d_in[10];
    const float* tf_W    = (const float*)d_in[11];
    const float* tf_b    = (const float*)d_in[12];
    const float* tg_W    = (const float*)d_in[13];
    const float* tg_b    = (const float*)d_in[14];
    const float* Wq = (const float*)d_in[15];
    const float* bq = (const float*)d_in[16];
    const float* Wk = (const float*)d_in[17];
    const float* bk = (const float*)d_in[18];
    const float* Wv = (const float*)d_in[19];
    const float* bv = (const float*)d_in[20];
    const float* Wo = (const float*)d_in[21];
    const float* bo = (const float*)d_in[22];
    const float* Ek = (const float*)d_in[23];
    const float* Ev = (const float*)d_in[24];
    const float* pos_emb = (const float*)d_in[25];
    const float* tfa_W = (const float*)d_in[26];
    const float* tfa_b = (const float*)d_in[27];
    const float* tga_W = (const float*)d_in[28];
    const float* tga_b = (const float*)d_in[29];

    float* d_W12   = symaddr(g_W12);
    float* d_b12   = symaddr(g_b12);
    float* d_Wtftg = symaddr(g_Wtftg);
    float* d_btftg = symaddr(g_btftg);
    float* d_Wab   = symaddr(g_Wab);
    float* d_bab   = symaddr(g_bab);
    float* d_h    = symaddr(g_h);
    float* d_agg  = symaddr(g_agg);
    float* d_g1   = symaddr(g_g1);
    float* d_xa   = symaddr(g_xa);
    float* d_xg   = symaddr(g_xg);
    float* d_tftg = symaddr(g_tftg);
    float* d_qin  = symaddr(g_qin);
    float* d_kin  = symaddr(g_kin);
    float* d_vin  = symaddr(g_vin);
    float* d_q    = symaddr(g_q);
    float* d_k    = symaddr(g_k);
    float* d_v    = symaddr(g_v);
    float* d_kc   = symaddr(g_kc);
    float* d_vc   = symaddr(g_vc);
    float* d_att  = symaddr(g_att);
    float* d_xf   = symaddr(g_xf);
    float* d_ab   = symaddr(g_ab);

    // 1. pack fused weight blocks
    pack2<<<(512 * 512 + 255) / 256, 256>>>(d_W12, gcn_W, gcnA2_W, d_b12, gcn_b, gcnA2_b, 512, 256);
    pack2<<<(256 * 256 + 255) / 256, 256>>>(d_Wtftg, tf_W, tg_W, d_btftg, tf_b, tg_b, 256, 128);
    pack2<<<(128 * 128 + 255) / 256, 256>>>(d_Wab, tfa_W, tga_W, d_bab, tfa_b, tga_b, 128, 64);

    // 2. h = data_feature @ [gcn_W | gcnA2_W]  (20000 x 512 x 512)
    sgemm<0><<<dim3(4, 157), 256>>>(data_feature, d_W12, nullptr, d_h, NN, 512, IND);

    // 3. degrees
    deg_init<<<(NN + 255) / 256, 256>>>();
    deg_count<<<(EE + 255) / 256, 256>>>(adj);
    deg_finish<<<(NN + 255) / 256, 256>>>();

    // 4. segment sum
    zero_kernel<<<(NN * 512 + 255) / 256, 256>>>(d_agg, NN * 512);
    edge_scatter<<<(EE * 128 + 255) / 256, 256>>>(adj);

    // 5. gcn finalize -> g1 (sigmoid), xa
    finalize_gcn<<<(NN * 512 + 255) / 256, 256>>>();

    // 6. x_g = leaky(g1 @ lin_W + lin_b); [tf|tg] = leaky(xa @ [tf_W|tg_W] + b)
    sgemm<1><<<dim3(1, 157), 256>>>(d_g1, lin_W, lin_b, d_xg, NN, 128, 256);
    sgemm<1><<<dim3(2, 157), 256>>>(d_xa, d_Wtftg, d_btftg, d_tftg, NN, 256, 256);

    // 7. q/k/v inputs (+pos emb) and projections
    build_qkv<<<(NN * 128 + 255) / 256, 256>>>(positions, pos_emb);
    sgemm<0><<<dim3(1, 157), 256>>>(d_qin, Wq, bq, d_q, NN, 128, 128);
    sgemm<0><<<dim3(1, 157), 256>>>(d_kin, Wk, bk, d_k, NN, 128, 128);
    sgemm<0><<<dim3(1, 157), 256>>>(d_vin, Wv, bv, d_v, NN, 128, 128);

    // 8. kc = Ek@k, vc = Ev@v  (split-K, atomic accumulate)
    zero_kernel<<<(DC * 128 * 2 + 255) / 256, 256>>>(d_kc, DC * 128);
    zero_kernel<<<(DC * 128 + 255) / 256, 256>>>(d_vc, DC * 128);
    splitk_ckv<<<dim3(2, 4, 50), 256>>>(Ek, Ev);

    // 9. fused attention
    attn_kernel<<<dim3(157, HEADS), 128>>>();

    // 10. x_f = att @ Wo + bo; [tfa|tga] = leaky(x_f @ [tfa_W|tga_W] + b)
    sgemm<0><<<dim3(1, 157), 256>>>(d_att, Wo, bo, d_xf, NN, 128, 128);
    sgemm<1><<<dim3(1, 157), 256>>>(d_xf, d_Wab, d_bab, d_ab, NN, 128, 128);

    // 11. norms + final cosine pairs
    norms_kernel<<<(NN + 255) / 256, 256>>>();
    final_pairs<<<(NT + 255) / 256, 256>>>(train_sample, (float*)d_out);
}

// round 7
// speedup vs baseline: 1.3432x; 1.3390x over previous
#include <cuda_runtime.h>
#include <math.h>

// ---------------- problem constants ----------------
constexpr int NN   = 20000;
constexpr int EE   = 320000;
constexpr int NT   = 200000;
constexpr int IND  = 512;   // INPUT_DIM
constexpr int HID  = 128;
constexpr int DC   = 256;
constexpr int HEADS = 8;
constexpr int DK   = 16;

// ---------------- scratch (static device globals; no runtime alloc) --------
__device__ float g_W12[512 * 512];
__device__ float g_b12[512];
__device__ float g_Wtftg[256 * 256];
__device__ float g_btftg[256];
__device__ float g_Wab[128 * 128];
__device__ float g_bab[128];

__device__ float g_h[(size_t)NN * 512];    // [h_gcn1 | h_gcn2]
__device__ float g_dinv[NN];

// CSR structures for the edge gather
__device__ int g_deg[NN];
__device__ int g_cnt[NN];
__device__ int g_off[NN + 1];
__device__ int g_esrc[EE];

__device__ float g_g1[(size_t)NN * 256];   // sigmoid(gcn1)
__device__ float g_xa[(size_t)NN * 256];   // gcn2 raw
__device__ float g_xg[(size_t)NN * 128];
__device__ float g_tftg[(size_t)NN * 256]; // [tf | tg]

__device__ float g_qin[(size_t)NN * 128];
__device__ float g_kin[(size_t)NN * 128];
__device__ float g_vin[(size_t)NN * 128];
__device__ float g_q[(size_t)NN * 128];
__device__ float g_k[(size_t)NN * 128];
__device__ float g_v[(size_t)NN * 128];

__device__ float g_kc[DC * 128];
__device__ float g_vc[DC * 128];

__device__ float g_att[(size_t)NN * 128];
__device__ float g_xf[(size_t)NN * 128];
__device__ float g_ab[(size_t)NN * 128];   // [tfa | tga], leaky applied
__device__ float g_na[NN];
__device__ float g_nb[NN];

// ---------------- small helpers ----------------
__global__ void zero_kernel(float* __restrict__ p, int n) {
    int i = blockIdx.x * blockDim.x + threadIdx.x;
    if (i < n) p[i] = 0.0f;
}

// pack W = [W1 | W2] (rows x 2*hc), b = [b1 | b2]
__global__ void pack2(float* __restrict__ W, const float* __restrict__ W1,
                      const float* __restrict__ W2, float* __restrict__ b,
                      const float* __restrict__ b1, const float* __restrict__ b2,
                      int rows, int hc) {
    int idx = blockIdx.x * blockDim.x + threadIdx.x;
    int tot = rows * 2 * hc;
    if (idx < tot) {
        int r = idx / (2 * hc);
        int c = idx - r * 2 * hc;
        W[idx] = (c < hc) ? W1[r * hc + c] : W2[r * hc + (c - hc)];
    }
    if (idx < 2 * hc) b[idx] = (idx < hc) ? b1[idx] : b2[idx - hc];
}

// ---------------- CSR construction ----------------
__global__ void deg_zero() {
    int i = blockIdx.x * blockDim.x + threadIdx.x;
    if (i < NN) { g_deg[i] = 0; g_cnt[i] = 0; }
}
__global__ void deg_count(const int* __restrict__ adj) {
    int e = blockIdx.x * blockDim.x + threadIdx.x;
    if (e < EE) atomicAdd(&g_deg[adj[EE + e]], 1);
}
// single-block exclusive scan over g_deg -> g_off; also dinv = rsqrt(1+deg)
__global__ void __launch_bounds__(1024) scan_offsets() {
    __shared__ int partial[1024];
    const int tid = threadIdx.x;
    const int PER = (NN + 1023) / 1024;   // 20
    const int base = tid * PER;
    int s = 0;
#pragma unroll
    for (int i = 0; i < PER; i++) {
        int idx = base + i;
        if (idx < NN) s += g_deg[idx];
    }
    partial[tid] = s;
    __syncthreads();
    for (int off = 1; off < 1024; off <<= 1) {
        int v = 0;
        if (tid >= off) v = partial[tid - off];
        __syncthreads();
        if (tid >= off) partial[tid] += v;
        __syncthreads();
    }
    int run = (tid > 0) ? partial[tid - 1] : 0;
#pragma unroll
    for (int i = 0; i < PER; i++) {
        int idx = base + i;
        if (idx < NN) {
            g_off[idx] = run;
            int d = g_deg[idx];
            run += d;
            g_dinv[idx] = rsqrtf(1.0f + (float)d);
        }
    }
    if (tid == 0) g_off[NN] = EE;
}
__global__ void fill_csr(const int* __restrict__ adj) {
    int e = blockIdx.x * blockDim.x + threadIdx.x;
    if (e >= EE) return;
    int s = adj[e];
    int d = adj[EE + e];
    int pos = g_off[d] + atomicAdd(&g_cnt[d], 1);
    g_esrc[pos] = s;
}

// ---------------- CSR gather + fused GCN finalize --------------------------
// one 128-thread block per dst node; each thread owns 4 contiguous columns.
// acc = sum_{e in in(d)} h[src_e] * dinv[src_e]*dinv[d]
// v   = acc + h[d]*dinv[d]^2 + b;  j<256 -> sigmoid into g1, else raw into xa
__global__ void __launch_bounds__(128) gcn_gather() {
    __shared__ int   s_src[128];
    __shared__ float s_coef[128];
    const int d = blockIdx.x;
    const int tid = threadIdx.x;
    const int beg = g_off[d];
    const int deg = g_off[d + 1] - beg;
    const float di = g_dinv[d];

    float4 acc = {0.f, 0.f, 0.f, 0.f};
    for (int c0 = 0; c0 < deg; c0 += 128) {
        int m = min(128, deg - c0);
        if (tid < m) {
            int s = g_esrc[beg + c0 + tid];
            s_src[tid] = s;
            s_coef[tid] = g_dinv[s] * di;
        }
        __syncthreads();
        int i = 0;
#pragma unroll 1
        for (; i + 4 <= m; i += 4) {
            const float4 h0 = *(const float4*)(g_h + (size_t)s_src[i + 0] * 512 + tid * 4);
            const float4 h1 = *(const float4*)(g_h + (size_t)s_src[i + 1] * 512 + tid * 4);
            const float4 h2 = *(const float4*)(g_h + (size_t)s_src[i + 2] * 512 + tid * 4);
            const float4 h3 = *(const float4*)(g_h + (size_t)s_src[i + 3] * 512 + tid * 4);
            float c0f = s_coef[i + 0], c1f = s_coef[i + 1];
            float c2f = s_coef[i + 2], c3f = s_coef[i + 3];
            acc.x += h0.x * c0f; acc.y += h0.y * c0f; acc.z += h0.z * c0f; acc.w += h0.w * c0f;
            acc.x += h1.x * c1f; acc.y += h1.y * c1f; acc.z += h1.z * c1f; acc.w += h1.w * c1f;
            acc.x += h2.x * c2f; acc.y += h2.y * c2f; acc.z += h2.z * c2f; acc.w += h2.w * c2f;
            acc.x += h3.x * c3f; acc.y += h3.y * c3f; acc.z += h3.z * c3f; acc.w += h3.w * c3f;
        }
        for (; i < m; i++) {
            const float4 hv = *(const float4*)(g_h + (size_t)s_src[i] * 512 + tid * 4);
            float cf = s_coef[i];
            acc.x += hv.x * cf; acc.y += hv.y * cf; acc.z += hv.z * cf; acc.w += hv.w * cf;
        }
        __syncthreads();
    }

    // fused finalize
    const int j = tid * 4;
    const float4 hd = *(const float4*)(g_h + (size_t)d * 512 + j);
    const float4 bb = *(const float4*)(g_b12 + j);
    const float d2 = di * di;
    float4 v;
    v.x = acc.x + hd.x * d2 + bb.x;
    v.y = acc.y + hd.y * d2 + bb.y;
    v.z = acc.z + hd.z * d2 + bb.z;
    v.w = acc.w + hd.w * d2 + bb.w;
    if (j < 256) {
        float4 o;
        o.x = 1.0f / (1.0f + __expf(-v.x));
        o.y = 1.0f / (1.0f + __expf(-v.y));
        o.z = 1.0f / (1.0f + __expf(-v.z));
        o.w = 1.0f / (1.0f + __expf(-v.w));
        *(float4*)(g_g1 + (size_t)d * 256 + j) = o;
    } else {
        *(float4*)(g_xa + (size_t)d * 256 + (j - 256)) = v;
    }
}

// ---------------- qkv inputs ----------------
__global__ void build_qkv(const int* __restrict__ positions,
                          const float* __restrict__ pos_emb) {
    int idx = blockIdx.x * blockDim.x + threadIdx.x;
    if (idx >= NN * 128) return;
    int n = idx >> 7;
    int j = idx & 127;
    float pe = pos_emb[positions[n] * 128 + j];
    g_qin[idx] = g_xg[idx] + pe;
    g_kin[idx] = g_tftg[(size_t)n * 256 + j] + pe;
    g_vin[idx] = g_tftg[(size_t)n * 256 + 128 + j];
}

// ---------------- generic fp32 SGEMM: C = act(A@B + bias) ------------------
// BM=BN=128, BK=8, 256 threads, 8x8 per thread. N % 128 == 0, K % 8 == 0.
template <int ACT>
__global__ void __launch_bounds__(256)
sgemm(const float* __restrict__ A, const float* __restrict__ B,
      const float* __restrict__ bias, float* __restrict__ C,
      int M, int N, int K) {
    __shared__ float As[8][128];
    __shared__ float Bs[8][128];
    const int tid = threadIdx.x;
    const int rowBase = blockIdx.y * 128;
    const int colBase = blockIdx.x * 128;

    const int lr = tid >> 1;           // 0..127 (A row within tile)
    const int lq = (tid & 1) * 4;      // 0 or 4 (k offset)
    const int br = tid >> 5;           // 0..7   (B k-row)
    const int bc = (tid & 31) * 4;     // 0..124 (B col)
    const int rm = tid >> 4;           // 0..15
    const int rn = tid & 15;           // 0..15

    const int arow = rowBase + lr;
    const bool aval = arow < M;
    const float* Aptr = A + (size_t)arow * K + lq;

    float acc[8][8];
#pragma unroll
    for (int i = 0; i < 8; i++)
#pragma unroll
        for (int j = 0; j < 8; j++) acc[i][j] = 0.0f;

    for (int k0 = 0; k0 < K; k0 += 8) {
        float4 a4 = aval ? *(const float4*)(Aptr + k0) : make_float4(0, 0, 0, 0);
        float4 b4 = *(const float4*)(B + (size_t)(k0 + br) * N + colBase + bc);
        __syncthreads();
        As[lq + 0][lr] = a4.x;
        As[lq + 1][lr] = a4.y;
        As[lq + 2][lr] = a4.z;
        As[lq + 3][lr] = a4.w;
        *(float4*)&Bs[br][bc] = b4;
        __syncthreads();
#pragma unroll
        for (int k = 0; k < 8; k++) {
            float4 a0 = *(float4*)&As[k][rm * 8];
            float4 a1 = *(float4*)&As[k][rm * 8 + 4];
            float4 b0 = *(float4*)&Bs[k][rn * 8];
            float4 b1 = *(float4*)&Bs[k][rn * 8 + 4];
            float av[8] = {a0.x, a0.y, a0.z, a0.w, a1.x, a1.y, a1.z, a1.w};
            float bv[8] = {b0.x, b0.y, b0.z, b0.w, b1.x, b1.y, b1.z, b1.w};
#pragma unroll
            for (int i = 0; i < 8; i++)
#pragma unroll
                for (int j = 0; j < 8; j++) acc[i][j] += av[i] * bv[j];
        }
    }

#pragma unroll
    for (int i = 0; i < 8; i++) {
        int row = rowBase + rm * 8 + i;
        if (row >= M) continue;
#pragma unroll
        for (int j4 = 0; j4 < 2; j4++) {
            int col = colBase + rn * 8 + j4 * 4;
            float4 o;
            float* op = &o.x;
#pragma unroll
            for (int j = 0; j < 4; j++) {
                float v = acc[i][j4 * 4 + j] + (bias ? bias[col + j] : 0.0f);
                if (ACT == 1) v = (v >= 0.0f) ? v : 0.01f * v;
                op[j] = v;
            }
            *(float4*)&C[(size_t)row * N + col] = o;
        }
    }
}

// ---------------- split-K GEMM for kc = Ek@k, vc = Ev@v --------------------
// M=256(DC), N=128, K=20000. BM=BN=64, BK=32, 25 k-iters per split, 25 splits.
__global__ void __launch_bounds__(256)
splitk_ckv(const float* __restrict__ Ekm, const float* __restrict__ Evm) {
    const int mat = blockIdx.z & 1;
    const int split = blockIdx.z >> 1;
    const float* Am = mat ? Evm : Ekm;
    const float* Xm = mat ? g_v : g_k;
    float* Cm = mat ? g_vc : g_kc;

    const int rowBase = blockIdx.y * 64;   // 4 tiles
    const int colBase = blockIdx.x * 64;   // 2 tiles
    const int tid = threadIdx.x;
    const int rm = tid >> 4, rn = tid & 15;

    __shared__ float As[32][64];
    __shared__ float Bs[32][64];

    float acc[4][4];
#pragma unroll
    for (int i = 0; i < 4; i++)
#pragma unroll
        for (int j = 0; j < 4; j++) acc[i][j] = 0.0f;

    const int kstart = split * 25 * 32;
    for (int it = 0; it < 25; it++) {
        int kbase = kstart + it * 32;
        __syncthreads();
#pragma unroll
        for (int pp = 0; pp < 2; pp++) {
            int p = tid + pp * 256;
            int row = p >> 3;
            int kq = (p & 7) * 4;
            float4 a4 = *(const float4*)(Am + (size_t)(rowBase + row) * NN + kbase + kq);
            As[kq + 0][row] = a4.x;
            As[kq + 1][row] = a4.y;
            As[kq + 2][row] = a4.z;
            As[kq + 3][row] = a4.w;
            int krow = p >> 4;
            int cq = (p & 15) * 4;
            float4 b4 = *(const float4*)(Xm + (size_t)(kbase + krow) * 128 + colBase + cq);
            *(float4*)&Bs[krow][cq] = b4;
        }
        __syncthreads();
#pragma unroll
        for (int k = 0; k < 32; k++) {
            float4 a4 = *(float4*)&As[k][rm * 4];
            float4 b4 = *(float4*)&Bs[k][rn * 4];
            float av[4] = {a4.x, a4.y, a4.z, a4.w};
            float bv[4] = {b4.x, b4.y, b4.z, b4.w};
#pragma unroll
            for (int i = 0; i < 4; i++)
#pragma unroll
                for (int j = 0; j < 4; j++) acc[i][j] += av[i] * bv[j];
        }
    }
#pragma unroll
    for (int i = 0; i < 4; i++)
#pragma unroll
        for (int j = 0; j < 4; j++)
            atomicAdd(&Cm[(size_t)(rowBase + rm * 4 + i) * 128 + colBase + rn * 4 + j],
                      acc[i][j]);
}

// ---------------- fused attention (online softmax) -------------------------
// block: 128 nodes x 1 head. kc/vc head slices staged in SMEM.
__global__ void __launch_bounds__(128)
attn_kernel() {
    __shared__ float4 kcs[DC][4];
    __shared__ float4 vcs[DC][4];
    const int h = blockIdx.y;
    const int tid = threadIdx.x;
    for (int p = tid; p < DC * 4; p += 128) {
        int c = p >> 2, d = p & 3;
        kcs[c][d] = *(const float4*)(g_kc + c * 128 + h * 16 + d * 4);
        vcs[c][d] = *(const float4*)(g_vc + c * 128 + h * 16 + d * 4);
    }
    __syncthreads();
    int n = blockIdx.x * 128 + tid;
    if (n >= NN) return;

    const float* qp = g_q + (size_t)n * 128 + h * 16;
    float4 q0 = *(const float4*)(qp + 0);
    float4 q1 = *(const float4*)(qp + 4);
    float4 q2 = *(const float4*)(qp + 8);
    float4 q3 = *(const float4*)(qp + 12);

    float m = -1e30f, s = 0.0f;
    float4 o0 = {0, 0, 0, 0}, o1 = {0, 0, 0, 0}, o2 = {0, 0, 0, 0}, o3 = {0, 0, 0, 0};

    for (int c = 0; c < DC; c++) {
        float4 k0 = kcs[c][0], k1 = kcs[c][1], k2 = kcs[c][2], k3 = kcs[c][3];
        float dot = q0.x * k0.x + q0.y * k0.y + q0.z * k0.z + q0.w * k0.w
                  + q1.x * k1.x + q1.y * k1.y + q1.z * k1.z + q1.w * k1.w
                  + q2.x * k2.x + q2.y * k2.y + q2.z * k2.z + q2.w * k2.w
                  + q3.x * k3.x + q3.y * k3.y + q3.z * k3.z + q3.w * k3.w;
        float sc = dot * 0.25f;
        float mn = fmaxf(m, sc);
        float al = __expf(m - mn);
        float p = __expf(sc - mn);
        s = s * al + p;
        float4 v0 = vcs[c][0], v1 = vcs[c][1], v2 = vcs[c][2], v3 = vcs[c][3];
        o0.x = o0.x * al + p * v0.x; o0.y = o0.y * al + p * v0.y;
        o0.z = o0.z * al + p * v0.z; o0.w = o0.w * al + p * v0.w;
        o1.x = o1.x * al + p * v1.x; o1.y = o1.y * al + p * v1.y;
        o1.z = o1.z * al + p * v1.z; o1.w = o1.w * al + p * v1.w;
        o2.x = o2.x * al + p * v2.x; o2.y = o2.y * al + p * v2.y;
        o2.z = o2.z * al + p * v2.z; o2.w = o2.w * al + p * v2.w;
        o3.x = o3.x * al + p * v3.x; o3.y = o3.y * al + p * v3.y;
        o3.z = o3.z * al + p * v3.z; o3.w = o3.w * al + p * v3.w;
        m = mn;
    }
    float inv = 1.0f / s;
    float* op = g_att + (size_t)n * 128 + h * 16;
    o0.x *= inv; o0.y *= inv; o0.z *= inv; o0.w *= inv;
    o1.x *= inv; o1.y *= inv; o1.z *= inv; o1.w *= inv;
    o2.x *= inv; o2.y *= inv; o2.z *= inv; o2.w *= inv;
    o3.x *= inv; o3.y *= inv; o3.z *= inv; o3.w *= inv;
    *(float4*)(op + 0) = o0;
    *(float4*)(op + 4) = o1;
    *(float4*)(op + 8) = o2;
    *(float4*)(op + 12) = o3;
}

// ---------------- row norms of tfa / tga ----------------
__global__ void norms_kernel() {
    int n = blockIdx.x * blockDim.x + threadIdx.x;
    if (n >= NN) return;
    const float4* a = (const float4*)(g_ab + (size_t)n * 128);
    float sa = 0.0f, sb = 0.0f;
#pragma unroll
    for (int i = 0; i < 16; i++) {
        float4 v = a[i];
        sa += v.x * v.x + v.y * v.y + v.z * v.z + v.w * v.w;
    }
#pragma unroll
    for (int i = 16; i < 32; i++) {
        float4 v = a[i];
        sb += v.x * v.x + v.y * v.y + v.z * v.z + v.w * v.w;
    }
    g_na[n] = sqrtf(sa);
    g_nb[n] = sqrtf(sb);
}

// ---------------- final cosine for 200K pairs ----------------
__global__ void final_pairs(const int* __restrict__ ts, float* __restrict__ out) {
    int t = blockIdx.x * blockDim.x + threadIdx.x;
    if (t >= NT) return;
    int i = ts[2 * t];
    int j = ts[2 * t + 1];
    const float4* a = (const float4*)(g_ab + (size_t)i * 128);
    const float4* b = (const float4*)(g_ab + (size_t)j * 128 + 64);
    float dot = 0.0f;
#pragma unroll
    for (int p = 0; p < 16; p++) {
        float4 av = a[p];
        float4 bv = b[p];
        dot += av.x * bv.x + av.y * bv.y + av.z * bv.z + av.w * bv.w;
    }
    out[t] = dot / fmaxf(g_na[i] * g_nb[j], 1e-8f);
}

// ---------------- host launcher ----------------
static float* symaddr(const void* sym) {
    void* p = nullptr;
    cudaGetSymbolAddress(&p, sym);
    return (float*)p;
}

extern "C" void kernel_launch(void* const* d_in, const int* in_sizes, int n_in,
                              void* d_out, int out_size) {
    const int*   train_sample = (const int*)d_in[1];
    const float* data_feature = (const float*)d_in[2];
    const int*   adj          = (const int*)d_in[3];
    const int*   positions    = (const int*)d_in[4];
    const float* gcn_W   = (const float*)d_in[5];
    const float* gcn_b   = (const float*)d_in[6];
    const float* gcnA2_W = (const float*)d_in[7];
    const float* gcnA2_b = (const float*)d_in[8];
    const float* lin_W   = (const float*)d_in[9];
    const float* lin_b   = (const float*)d_in[10];
    const float* tf_W    = (const float*)d_in[11];
    const float* tf_b    = (const float*)d_in[12];
    const float* tg_W    = (const float*)d_in[13];
    const float* tg_b    = (const float*)d_in[14];
    const float* Wq = (const float*)d_in[15];
    const float* bq = (const float*)d_in[16];
    const float* Wk = (const float*)d_in[17];
    const float* bk = (const float*)d_in[18];
    const float* Wv = (const float*)d_in[19];
    const float* bv = (const float*)d_in[20];
    const float* Wo = (const float*)d_in[21];
    const float* bo = (const float*)d_in[22];
    const float* Ek = (const float*)d_in[23];
    const float* Ev = (const float*)d_in[24];
    const float* pos_emb = (const float*)d_in[25];
    const float* tfa_W = (const float*)d_in[26];
    const float* tfa_b = (const float*)d_in[27];
    const float* tga_W = (const float*)d_in[28];
    const float* tga_b = (const float*)d_in[29];

    float* d_W12   = symaddr(g_W12);
    float* d_b12   = symaddr(g_b12);
    float* d_Wtftg = symaddr(g_Wtftg);
    float* d_btftg = symaddr(g_btftg);
    float* d_Wab   = symaddr(g_Wab);
    float* d_bab   = symaddr(g_bab);
    float* d_h    = symaddr(g_h);
    float* d_g1   = symaddr(g_g1);
    float* d_xa   = symaddr(g_xa);
    float* d_xg   = symaddr(g_xg);
    float* d_tftg = symaddr(g_tftg);
    float* d_qin  = symaddr(g_qin);
    float* d_kin  = symaddr(g_kin);
    float* d_vin  = symaddr(g_vin);
    float* d_q    = symaddr(g_q);
    float* d_k    = symaddr(g_k);
    float* d_v    = symaddr(g_v);
    float* d_kc   = symaddr(g_kc);
    float* d_vc   = symaddr(g_vc);
    float* d_att  = symaddr(g_att);
    float* d_xf   = symaddr(g_xf);
    float* d_ab   = symaddr(g_ab);

    // 1. pack fused weight blocks
    pack2<<<(512 * 512 + 255) / 256, 256>>>(d_W12, gcn_W, gcnA2_W, d_b12, gcn_b, gcnA2_b, 512, 256);
    pack2<<<(256 * 256 + 255) / 256, 256>>>(d_Wtftg, tf_W, tg_W, d_btftg, tf_b, tg_b, 256, 128);
    pack2<<<(128 * 128 + 255) / 256, 256>>>(d_Wab, tfa_W, tga_W, d_bab, tfa_b, tga_b, 128, 64);

    // 2. CSR construction (overlaps conceptually with GEMM; stream-ordered)
    deg_zero<<<(NN + 255) / 256, 256>>>();
    deg_count<<<(EE + 255) / 256, 256>>>(adj);
    scan_offsets<<<1, 1024>>>();
    fill_csr<<<(EE + 255) / 256, 256>>>(adj);

    // 3. h = data_feature @ [gcn_W | gcnA2_W]  (20000 x 512 x 512)
    sgemm<0><<<dim3(4, 157), 256>>>(data_feature, d_W12, nullptr, d_h, NN, 512, IND);

    // 4. CSR gather + fused finalize -> g1 (sigmoid), xa
    gcn_gather<<<NN, 128>>>();

    // 5. x_g = leaky(g1 @ lin_W + lin_b); [tf|tg] = leaky(xa @ [tf_W|tg_W] + b)
    sgemm<1><<<dim3(1, 157), 256>>>(d_g1, lin_W, lin_b, d_xg, NN, 128, 256);
    sgemm<1><<<dim3(2, 157), 256>>>(d_xa, d_Wtftg, d_btftg, d_tftg, NN, 256, 256);

    // 6. q/k/v inputs (+pos emb) and projections
    build_qkv<<<(NN * 128 + 255) / 256, 256>>>(positions, pos_emb);
    sgemm<0><<<dim3(1, 157), 256>>>(d_qin, Wq, bq, d_q, NN, 128, 128);
    sgemm<0><<<dim3(1, 157), 256>>>(d_kin, Wk, bk, d_k, NN, 128, 128);
    sgemm<0><<<dim3(1, 157), 256>>>(d_vin, Wv, bv, d_v, NN, 128, 128);

    // 7. kc = Ek@k, vc = Ev@v  (split-K, atomic accumulate)
    zero_kernel<<<(DC * 128 * 2 + 255) / 256, 256>>>(d_kc, DC * 128);
    zero_kernel<<<(DC * 128 + 255) / 256, 256>>>(d_vc, DC * 128);
    splitk_ckv<<<dim3(2, 4, 50), 256>>>(Ek, Ev);

    // 8. fused attention
    attn_kernel<<<dim3(157, HEADS), 128>>>();

    // 9. x_f = att @ Wo + bo; [tfa|tga] = leaky(x_f @ [tfa_W|tga_W] + b)
    sgemm<0><<<dim3(1, 157), 256>>>(d_att, Wo, bo, d_xf, NN, 128, 128);
    sgemm<1><<<dim3(1, 157), 256>>>(d_xf, d_Wab, d_bab, d_ab, NN, 128, 128);

    // 10. norms + final cosine pairs
    norms_kernel<<<(NN + 255) / 256, 256>>>();
    final_pairs<<<(NT + 255) / 256, 256>>>(train_sample, (float*)d_out);
}